// round 5
// baseline (speedup 1.0000x reference)
#include <cuda_runtime.h>
#include <math.h>

#define BB 8
#define CC 2048
#define DD 64
#define LL 3
#define HH 4
#define DHH 16
#define OUTN 10

typedef unsigned long long u64;

// ---- scratch (device globals; no allocs allowed) ----
__device__ float g_h[BB*CC*DD];          // [B,C,D]
__device__ float g_q[BB*HH*CC*DHH];      // [B,H,C,16]
__device__ float g_k[BB*HH*CC*DHH];
__device__ float g_v[BB*HH*CC*DHH];
__device__ float g_qp[BB*HH*CC*DHH];
__device__ float g_kp[BB*HH*CC*DHH];
__device__ float g_attn[BB*CC*DD];       // [B,C,D] head-interleaved
__device__ float g_t[BB*CC*4*DD];        // FFN hidden [B,C,256]

// ---- f32x2 packed helpers ----
__device__ __forceinline__ u64 fma2(u64 a, u64 b, u64 c){
    u64 d; asm("fma.rn.f32x2 %0, %1, %2, %3;" : "=l"(d) : "l"(a), "l"(b), "l"(c)); return d;
}
__device__ __forceinline__ u64 add2(u64 a, u64 b){
    u64 d; asm("add.rn.f32x2 %0, %1, %2;" : "=l"(d) : "l"(a), "l"(b)); return d;
}
__device__ __forceinline__ u64 mul2(u64 a, u64 b){
    u64 d; asm("mul.rn.f32x2 %0, %1, %2;" : "=l"(d) : "l"(a), "l"(b)); return d;
}
__device__ __forceinline__ u64 pk2(float a, float b){
    u64 d; asm("mov.b64 %0, {%1, %2};" : "=l"(d) : "f"(a), "f"(b)); return d;
}
__device__ __forceinline__ void upk2(u64 v, float& a, float& b){
    asm("mov.b64 {%0, %1}, %2;" : "=f"(a), "=f"(b) : "l"(v));
}
__device__ __forceinline__ float tanh_ap(float x){
    float r; asm("tanh.approx.f32 %0, %1;" : "=f"(r) : "f"(x)); return r;
}

// exact gelu (used outside the attention hot loop)
__device__ __forceinline__ float gelu_f(float x){
    return 0.5f*x*(1.0f + erff(x*0.70710678118654752440f));
}

// ---- K0: binding encoder ----
__global__ void k_encode(const float* __restrict__ x, const float* __restrict__ role,
                         const float* __restrict__ fw){
    int idx = blockIdx.x*256 + threadIdx.x;
    if (idx >= BB*CC*DD) return;
    int d = idx & 63;
    int bc = idx >> 6;
    float xl = log1pf(fmaxf(x[bc], 0.0f));
    float f = gelu_f(xl * fw[d]);
    g_h[idx] = role[(bc & (CC-1))*DD + d] * f;
}

// ---- K1: QKV projections -> [B,H,C,16] layout ----
__global__ void k_qkv(const float* __restrict__ qw, const float* __restrict__ qb,
                      const float* __restrict__ kw, const float* __restrict__ kb,
                      const float* __restrict__ vw, const float* __restrict__ vb, int l){
    __shared__ float hs[64][65];
    __shared__ float ws[64][65];
    int b = blockIdx.y, c0 = blockIdx.x*64;
    const float* hp = g_h + (b*CC + c0)*DD;
    for (int t = threadIdx.x; t < 4096; t += 256) hs[t>>6][t&63] = hp[t];
    int o  = threadIdx.x & 63;
    int rg = threadIdx.x >> 6;
    int hh = o >> 4, m = o & 15;
    const float* Wm[3] = { qw + l*4096, kw + l*4096, vw + l*4096 };
    const float* Bm[3] = { qb + l*64,   kb + l*64,   vb + l*64 };
    float* Om[3] = { g_q, g_k, g_v };
    #pragma unroll
    for (int mat = 0; mat < 3; mat++){
        __syncthreads();
        for (int t = threadIdx.x; t < 4096; t += 256) ws[t>>6][t&63] = Wm[mat][t];
        __syncthreads();
        float acc[16];
        float bias = Bm[mat][o];
        #pragma unroll
        for (int r = 0; r < 16; r++) acc[r] = bias;
        for (int n = 0; n < 64; n++){
            float w = ws[o][n];
            #pragma unroll
            for (int r = 0; r < 16; r++) acc[r] += hs[rg*16+r][n]*w;
        }
        float* op = Om[mat] + ((size_t)(b*HH + hh)*CC + c0 + rg*16)*DHH + m;
        #pragma unroll
        for (int r = 0; r < 16; r++) op[r*DHH] = acc[r];
    }
}

// ---- K1b: qp = q@w1q^T, kp = k@w1k^T ----
__global__ void k_qpkp(const float* __restrict__ w1_, int l){
    __shared__ float qs[256][17];
    __shared__ float ks2[256][17];
    __shared__ float w1qs[16][16], w1ks[16][16];
    int base = blockIdx.x*256;            // over B*H*C
    for (int t = threadIdx.x; t < 4096; t += 256){
        qs[t>>4][t&15]  = g_q[(size_t)base*16 + t];
        ks2[t>>4][t&15] = g_k[(size_t)base*16 + t];
    }
    {
        int mm = threadIdx.x >> 4, nn = threadIdx.x & 15;
        w1qs[mm][nn] = w1_[(l*16+mm)*48 + nn];
        w1ks[mm][nn] = w1_[(l*16+mm)*48 + 16 + nn];
    }
    __syncthreads();
    int tid = threadIdx.x;
    float qv[16], kv[16];
    #pragma unroll
    for (int n = 0; n < 16; n++){ qv[n] = qs[tid][n]; kv[n] = ks2[tid][n]; }
    float aq[16], ak[16];
    #pragma unroll
    for (int mm = 0; mm < 16; mm++){
        float a = 0.f, c = 0.f;
        #pragma unroll
        for (int n = 0; n < 16; n++){ a += w1qs[mm][n]*qv[n]; c += w1ks[mm][n]*kv[n]; }
        aq[mm] = a; ak[mm] = c;
    }
    __syncthreads();
    #pragma unroll
    for (int mm = 0; mm < 16; mm++){ qs[tid][mm] = aq[mm]; ks2[tid][mm] = ak[mm]; }
    __syncthreads();
    for (int t = threadIdx.x; t < 4096; t += 256){
        g_qp[(size_t)base*16 + t] = qs[t>>4][t&15];
        g_kp[(size_t)base*16 + t] = ks2[t>>4][t&15];
    }
}

// ---- K2: second-order attention ----
// block = 256 threads = 8 warps = 4 queries (2 warps/query).
// Each lane owns ONE packed pair of keys; a warp covers 64 keys; the warp-pair
// covers the 128-key tile. qw read as LDS.128 broadcast (ulonglong2).
__global__ void __launch_bounds__(256, 2) k_attn(const float* __restrict__ w1_,
        const float* __restrict__ b1_, const float* __restrict__ w2_,
        const float* __restrict__ b2_, int l){
    __shared__ __align__(16) u64 qw2[4][16][16];   // {w,w} per query
    __shared__ __align__(16) u64 qp2[4][16];       // {qp+b1, qp+b1}
    __shared__ __align__(16) u64 w22[16];          // {w2*0.25, w2*0.25}
    __shared__ __align__(16) u64 k2s[16][65];      // [n][jpair] transposed, pad
    __shared__ __align__(16) u64 kp2s[16][65];     // [m][jpair]
    __shared__ __align__(16) u64 v2s[16][65];      // [m][jpair]
    __shared__ float redS[4][2];
    __shared__ float redO[4][2][16];

    int b = blockIdx.z, h = blockIdx.y, i0 = blockIdx.x*4;
    int tid = threadIdx.x;
    int warp = tid >> 5, lane = tid & 31;
    int q = warp >> 1, hw = warp & 1;
    int off = hw*32 + lane;               // key-pair slot 0..63
    int bh = b*HH + h;
    const float* qbase  = g_q  + (size_t)(bh*CC + i0)*16;
    const float* qpb_g  = g_qp + (size_t)(bh*CC + i0)*16;

    if (tid < 64){
        int w = tid >> 4, mm = tid & 15;
        float v = qpb_g[w*16+mm] + b1_[l*16+mm];
        qp2[w][mm] = pk2(v, v);
    }
    if (tid >= 64 && tid < 80){
        float v = w2_[l*16 + (tid-64)]*0.25f;
        w22[tid-64] = pk2(v, v);
    }
    for (int t = tid; t < 1024; t += 256){
        int w = t >> 8, mn = t & 255, mm = mn >> 4, nn = mn & 15;
        float v = qbase[w*16+nn] * w1_[(l*16+mm)*48 + 32 + nn];
        qw2[w][mm][nn] = pk2(v, v);
    }
    float b2s = b2_[l]*0.25f;

    const u64 C0 = pk2(0.7978845608f, 0.7978845608f);
    const u64 C1 = pk2(0.03567740814f, 0.03567740814f);
    const u64 HF = pk2(0.5f, 0.5f);

    u64 outp[16];
    #pragma unroll
    for (int mm = 0; mm < 16; mm++) outp[mm] = 0ull;
    u64 S = 0ull;

    const float* kb  = g_k  + (size_t)bh*CC*16;
    const float* kpb = g_kp + (size_t)bh*CC*16;
    const float* vb  = g_v  + (size_t)bh*CC*16;
    float* k2f  = (float*)k2s;    // row stride 130 floats
    float* kp2f = (float*)kp2s;
    float* v2f  = (float*)v2s;

    const u64* kprow = &kp2s[0][off];
    const u64* vrow  = &v2s[0][off];
    const u64* qpq   = qp2[q];

    for (int j0 = 0; j0 < CC; j0 += 128){
        __syncthreads();
        // staging: 2048 floats per array, float4 loads, transposed scalar stores
        #pragma unroll
        for (int it = 0; it < 2; it++){
            int t = (tid + it*256)*4;           // 0..2044, step 4
            int n = t & 15, j = t >> 4;
            float4 vk = *(const float4*)&kb [j0*16 + t];
            float4 vp = *(const float4*)&kpb[j0*16 + t];
            float4 vv = *(const float4*)&vb [j0*16 + t];
            k2f [(n+0)*130 + j] = vk.x; k2f [(n+1)*130 + j] = vk.y;
            k2f [(n+2)*130 + j] = vk.z; k2f [(n+3)*130 + j] = vk.w;
            kp2f[(n+0)*130 + j] = vp.x; kp2f[(n+1)*130 + j] = vp.y;
            kp2f[(n+2)*130 + j] = vp.z; kp2f[(n+3)*130 + j] = vp.w;
            v2f [(n+0)*130 + j] = vv.x; v2f [(n+1)*130 + j] = vv.y;
            v2f [(n+2)*130 + j] = vv.z; v2f [(n+3)*130 + j] = vv.w;
        }
        __syncthreads();

        u64 kj[16];
        #pragma unroll
        for (int n = 0; n < 16; n++) kj[n] = k2s[n][off];

        u64 sc = pk2(b2s, b2s);
        #pragma unroll
        for (int mm = 0; mm < 16; mm++){
            u64 ra = add2(qpq[mm], kprow[mm*65]);
            u64 rb = 0ull;
            const ulonglong2* qwm = (const ulonglong2*)qw2[q][mm];
            #pragma unroll
            for (int n2 = 0; n2 < 8; n2++){
                ulonglong2 w = qwm[n2];
                ra = fma2(w.x, kj[2*n2],   ra);
                rb = fma2(w.y, kj[2*n2+1], rb);
            }
            u64 r  = add2(ra, rb);
            u64 t2 = mul2(r, r);
            u64 a  = fma2(C1, t2, C0);
            u64 u  = mul2(r, a);
            float u0, u1; upk2(u, u0, u1);
            u64 th = pk2(tanh_ap(u0), tanh_ap(u1));
            u64 hx = mul2(r, HF);
            u64 g  = fma2(hx, th, hx);
            sc = fma2(w22[mm], g, sc);
        }
        // fixed-base softmax (scores bounded far below exp overflow)
        float s0, s1; upk2(sc, s0, s1);
        u64 p = pk2(__expf(s0), __expf(s1));
        S = add2(S, p);
        #pragma unroll
        for (int mm = 0; mm < 16; mm++)
            outp[mm] = fma2(p, vrow[mm*65], outp[mm]);
    }

    float sl, sh; upk2(S, sl, sh);
    float Ssum = sl + sh;
    #pragma unroll
    for (int o2 = 16; o2 > 0; o2 >>= 1)
        Ssum += __shfl_xor_sync(0xffffffffu, Ssum, o2);
    float res = 0.f;
    #pragma unroll
    for (int mm = 0; mm < 16; mm++){
        float a, bq; upk2(outp[mm], a, bq);
        float t = a + bq;
        #pragma unroll
        for (int o2 = 16; o2 > 0; o2 >>= 1)
            t += __shfl_xor_sync(0xffffffffu, t, o2);
        if (lane == mm) res = t;
    }
    if (lane < 16) redO[q][hw][lane] = res;
    if (lane == 0) redS[q][hw] = Ssum;
    __syncthreads();
    if (hw == 0 && lane < 16){
        float num = redO[q][0][lane] + redO[q][1][lane];
        float den = redS[q][0] + redS[q][1];
        g_attn[((size_t)(b*CC + i0 + q))*DD + h*16 + lane] = num / den;
    }
}

// ---- K3: out projection + residual + LN1 ----
__global__ void k_outln(const float* __restrict__ ow, const float* __restrict__ ob,
                        const float* __restrict__ g1, const float* __restrict__ b1g, int l){
    __shared__ float as_[64][65];
    __shared__ float ws[64][65];
    int b = blockIdx.y, c0 = blockIdx.x*64;
    const float* ap = g_attn + (b*CC + c0)*DD;
    for (int t = threadIdx.x; t < 4096; t += 256){
        as_[t>>6][t&63] = ap[t];
        ws[t>>6][t&63]  = ow[l*4096 + t];
    }
    __syncthreads();
    int o = threadIdx.x & 63, rg = threadIdx.x >> 6;
    float acc[16];
    float bias = ob[l*64 + o];
    #pragma unroll
    for (int r = 0; r < 16; r++) acc[r] = bias;
    for (int n = 0; n < 64; n++){
        float w = ws[o][n];
        #pragma unroll
        for (int r = 0; r < 16; r++) acc[r] += as_[rg*16+r][n]*w;
    }
    const float* hp = g_h + (b*CC + c0)*DD;
    float resv[16];
    #pragma unroll
    for (int r = 0; r < 16; r++) resv[r] = acc[r] + hp[(rg*16+r)*64 + o];
    __syncthreads();
    #pragma unroll
    for (int r = 0; r < 16; r++) as_[rg*16+r][o] = resv[r];
    __syncthreads();
    if (threadIdx.x < 64){
        int r = threadIdx.x;
        float mean = 0.f;
        #pragma unroll
        for (int d = 0; d < 64; d++) mean += as_[r][d];
        mean *= (1.0f/64.0f);
        float var = 0.f;
        #pragma unroll
        for (int d = 0; d < 64; d++){ float t = as_[r][d]-mean; var += t*t; }
        var *= (1.0f/64.0f);
        float rstd = rsqrtf(var + 1e-5f);
        float* hout = g_h + ((size_t)(b*CC + c0 + r))*DD;
        for (int d = 0; d < 64; d++)
            hout[d] = (as_[r][d]-mean)*rstd*g1[l*64+d] + b1g[l*64+d];
    }
}

// ---- K4a: FFN layer 1 (64 -> 256) + GELU ----
__global__ void k_ffn1(const float* __restrict__ fw, const float* __restrict__ fb, int l){
    __shared__ float hs[64][65];
    __shared__ float ws[64][65];
    int b = blockIdx.y, c0 = blockIdx.x*64;
    const float* hp = g_h + (b*CC + c0)*DD;
    for (int t = threadIdx.x; t < 4096; t += 256) hs[t>>6][t&63] = hp[t];
    int o = threadIdx.x & 63, rg = threadIdx.x >> 6;
    for (int oc = 0; oc < 4; oc++){
        __syncthreads();
        for (int t = threadIdx.x; t < 4096; t += 256) ws[t>>6][t&63] = fw[l*16384 + oc*4096 + t];
        __syncthreads();
        int j = oc*64 + o;
        float acc[16];
        float bias = fb[l*256 + j];
        #pragma unroll
        for (int r = 0; r < 16; r++) acc[r] = bias;
        for (int n = 0; n < 64; n++){
            float w = ws[o][n];
            #pragma unroll
            for (int r = 0; r < 16; r++) acc[r] += hs[rg*16+r][n]*w;
        }
        float* tp = g_t + ((size_t)(b*CC + c0 + rg*16))*256 + j;
        #pragma unroll
        for (int r = 0; r < 16; r++) tp[r*256] = gelu_f(acc[r]);
    }
}

// ---- K4b: FFN layer 2 (256 -> 64) + residual + LN2 ----
__global__ void k_ffn2(const float* __restrict__ fw, const float* __restrict__ fb,
                       const float* __restrict__ g2, const float* __restrict__ b2g, int l){
    __shared__ float ts[64][65];
    __shared__ float ws[64][65];
    int b = blockIdx.y, c0 = blockIdx.x*64;
    int o = threadIdx.x & 63, rg = threadIdx.x >> 6;
    float acc[16];
    float bias = fb[l*64 + o];
    #pragma unroll
    for (int r = 0; r < 16; r++) acc[r] = bias;
    for (int nc = 0; nc < 4; nc++){
        __syncthreads();
        for (int t = threadIdx.x; t < 4096; t += 256){
            int row = t >> 6, col = t & 63;
            ts[row][col] = g_t[((size_t)(b*CC + c0 + row))*256 + nc*64 + col];
            ws[row][col] = fw[l*16384 + row*256 + nc*64 + col];
        }
        __syncthreads();
        for (int n = 0; n < 64; n++){
            float w = ws[o][n];
            #pragma unroll
            for (int r = 0; r < 16; r++) acc[r] += ts[rg*16+r][n]*w;
        }
    }
    const float* hp = g_h + (b*CC + c0)*DD;
    float resv[16];
    #pragma unroll
    for (int r = 0; r < 16; r++) resv[r] = acc[r] + hp[(rg*16+r)*64 + o];
    __syncthreads();
    #pragma unroll
    for (int r = 0; r < 16; r++) ts[rg*16+r][o] = resv[r];
    __syncthreads();
    if (threadIdx.x < 64){
        int r = threadIdx.x;
        float mean = 0.f;
        #pragma unroll
        for (int d = 0; d < 64; d++) mean += ts[r][d];
        mean *= (1.0f/64.0f);
        float var = 0.f;
        #pragma unroll
        for (int d = 0; d < 64; d++){ float t = ts[r][d]-mean; var += t*t; }
        var *= (1.0f/64.0f);
        float rstd = rsqrtf(var + 1e-5f);
        float* hout = g_h + ((size_t)(b*CC + c0 + r))*DD;
        for (int d = 0; d < 64; d++)
            hout[d] = (ts[r][d]-mean)*rstd*g2[l*64+d] + b2g[l*64+d];
    }
}

// ---- K5: task-query readout ----
__global__ void k_readout(const float* __restrict__ tq, const float* __restrict__ hw,
                          const float* __restrict__ hbias, float* __restrict__ outp){
    __shared__ float s[CC];
    __shared__ float red[256];
    __shared__ float pooled[DD];
    __shared__ float tqs[DD];
    int b = blockIdx.x, tid = threadIdx.x;
    if (tid < 64) tqs[tid] = tq[tid];
    __syncthreads();
    const float* hbase = g_h + (size_t)b*CC*DD;
    for (int c = tid; c < CC; c += 256){
        float acc = 0.f;
        const float* hr = hbase + c*DD;
        for (int d = 0; d < 64; d++) acc += hr[d]*tqs[d];
        s[c] = acc*0.125f;   // 1/sqrt(64)
    }
    __syncthreads();
    float m = -1e30f;
    for (int c = tid; c < CC; c += 256) m = fmaxf(m, s[c]);
    red[tid] = m; __syncthreads();
    for (int st = 128; st > 0; st >>= 1){ if (tid < st) red[tid] = fmaxf(red[tid], red[tid+st]); __syncthreads(); }
    float mx = red[0];
    __syncthreads();
    float ss = 0.f;
    for (int c = tid; c < CC; c += 256){ float e = expf(s[c]-mx); s[c] = e; ss += e; }
    red[tid] = ss; __syncthreads();
    for (int st = 128; st > 0; st >>= 1){ if (tid < st) red[tid] += red[tid+st]; __syncthreads(); }
    float sum = red[0];
    __syncthreads();
    if (tid < 64){
        float acc = 0.f;
        for (int c = 0; c < CC; c++) acc += s[c]*hbase[c*DD + tid];
        pooled[tid] = acc / sum;
    }
    __syncthreads();
    if (tid < OUTN){
        float acc = hbias[tid];
        for (int d = 0; d < 64; d++) acc += pooled[d]*hw[tid*64+d];
        outp[b*OUTN + tid] = acc;
    }
}

extern "C" void kernel_launch(void* const* d_in, const int* in_sizes, int n_in,
                              void* d_out, int out_size){
    const float* x      = (const float*)d_in[0];
    const float* role   = (const float*)d_in[1];
    const float* fw     = (const float*)d_in[2];
    const float* q_w    = (const float*)d_in[3];
    const float* q_b    = (const float*)d_in[4];
    const float* k_w    = (const float*)d_in[5];
    const float* k_b    = (const float*)d_in[6];
    const float* v_w    = (const float*)d_in[7];
    const float* v_b    = (const float*)d_in[8];
    const float* w1     = (const float*)d_in[9];
    const float* b1     = (const float*)d_in[10];
    const float* w2     = (const float*)d_in[11];
    const float* b2     = (const float*)d_in[12];
    const float* out_w  = (const float*)d_in[13];
    const float* out_b  = (const float*)d_in[14];
    const float* ln1_g  = (const float*)d_in[15];
    const float* ln1_b  = (const float*)d_in[16];
    const float* f1_w   = (const float*)d_in[17];
    const float* f1_b   = (const float*)d_in[18];
    const float* f2_w   = (const float*)d_in[19];
    const float* f2_b   = (const float*)d_in[20];
    const float* ln2_g  = (const float*)d_in[21];
    const float* ln2_b  = (const float*)d_in[22];
    const float* task_q = (const float*)d_in[23];
    const float* head_w = (const float*)d_in[24];
    const float* head_b = (const float*)d_in[25];
    float* outp = (float*)d_out;

    k_encode<<<(BB*CC*DD + 255)/256, 256>>>(x, role, fw);
    for (int l = 0; l < LL; l++){
        dim3 g1(CC/64, BB);
        k_qkv<<<g1, 256>>>(q_w, q_b, k_w, k_b, v_w, v_b, l);
        k_qpkp<<<(BB*HH*CC)/256, 256>>>(w1, l);
        dim3 ga(CC/4, HH, BB);
        k_attn<<<ga, 256>>>(w1, b1, w2, b2, l);
        k_outln<<<g1, 256>>>(out_w, out_b, ln1_g, ln1_b, l);
        k_ffn1<<<g1, 256>>>(f1_w, f1_b, l);
        k_ffn2<<<g1, 256>>>(f2_w, f2_b, ln2_g, ln2_b, l);
    }
    k_readout<<<BB, 256>>>(task_q, head_w, head_b, outp);
}

// round 7
// speedup vs baseline: 1.3336x; 1.3336x over previous
#include <cuda_runtime.h>
#include <math.h>

#define BB 8
#define CC 2048
#define DD 64
#define LL 3
#define HH 4
#define DHH 16
#define OUTN 10

typedef unsigned long long u64;

// ---- scratch (device globals; no allocs allowed) ----
__device__ float g_h[BB*CC*DD];          // [B,C,D]
__device__ float g_q[BB*HH*CC*DHH];      // [B,H,C,16]
__device__ float g_k[BB*HH*CC*DHH];
__device__ float g_v[BB*HH*CC*DHH];
__device__ float g_qp[BB*HH*CC*DHH];
__device__ float g_kp[BB*HH*CC*DHH];
__device__ float g_attn[BB*CC*DD];       // [B,C,D] head-interleaved
__device__ float g_t[BB*CC*4*DD];        // FFN hidden [B,C,256]

// ---- f32x2 packed helpers ----
__device__ __forceinline__ u64 fma2(u64 a, u64 b, u64 c){
    u64 d; asm("fma.rn.f32x2 %0, %1, %2, %3;" : "=l"(d) : "l"(a), "l"(b), "l"(c)); return d;
}
__device__ __forceinline__ u64 add2(u64 a, u64 b){
    u64 d; asm("add.rn.f32x2 %0, %1, %2;" : "=l"(d) : "l"(a), "l"(b)); return d;
}
__device__ __forceinline__ u64 mul2(u64 a, u64 b){
    u64 d; asm("mul.rn.f32x2 %0, %1, %2;" : "=l"(d) : "l"(a), "l"(b)); return d;
}
__device__ __forceinline__ u64 pk2(float a, float b){
    u64 d; asm("mov.b64 %0, {%1, %2};" : "=l"(d) : "f"(a), "f"(b)); return d;
}
__device__ __forceinline__ void upk2(u64 v, float& a, float& b){
    asm("mov.b64 {%0, %1}, %2;" : "=f"(a), "=f"(b) : "l"(v));
}
__device__ __forceinline__ float tanh_ap(float x){
    float r; asm("tanh.approx.f32 %0, %1;" : "=f"(r) : "f"(x)); return r;
}

// exact gelu (used outside the attention hot loop)
__device__ __forceinline__ float gelu_f(float x){
    return 0.5f*x*(1.0f + erff(x*0.70710678118654752440f));
}

// ---- K0: binding encoder ----
__global__ void k_encode(const float* __restrict__ x, const float* __restrict__ role,
                         const float* __restrict__ fw){
    int idx = blockIdx.x*256 + threadIdx.x;
    if (idx >= BB*CC*DD) return;
    int d = idx & 63;
    int bc = idx >> 6;
    float xl = log1pf(fmaxf(x[bc], 0.0f));
    float f = gelu_f(xl * fw[d]);
    g_h[idx] = role[(bc & (CC-1))*DD + d] * f;
}

// ---- K1: QKV projections -> [B,H,C,16] layout ----
__global__ void k_qkv(const float* __restrict__ qw, const float* __restrict__ qb,
                      const float* __restrict__ kw, const float* __restrict__ kb,
                      const float* __restrict__ vw, const float* __restrict__ vb, int l){
    __shared__ float hs[64][65];
    __shared__ float ws[64][65];
    int b = blockIdx.y, c0 = blockIdx.x*64;
    const float* hp = g_h + (b*CC + c0)*DD;
    for (int t = threadIdx.x; t < 4096; t += 256) hs[t>>6][t&63] = hp[t];
    int o  = threadIdx.x & 63;
    int rg = threadIdx.x >> 6;
    int hh = o >> 4, m = o & 15;
    const float* Wm[3] = { qw + l*4096, kw + l*4096, vw + l*4096 };
    const float* Bm[3] = { qb + l*64,   kb + l*64,   vb + l*64 };
    float* Om[3] = { g_q, g_k, g_v };
    #pragma unroll
    for (int mat = 0; mat < 3; mat++){
        __syncthreads();
        for (int t = threadIdx.x; t < 4096; t += 256) ws[t>>6][t&63] = Wm[mat][t];
        __syncthreads();
        float acc[16];
        float bias = Bm[mat][o];
        #pragma unroll
        for (int r = 0; r < 16; r++) acc[r] = bias;
        for (int n = 0; n < 64; n++){
            float w = ws[o][n];
            #pragma unroll
            for (int r = 0; r < 16; r++) acc[r] += hs[rg*16+r][n]*w;
        }
        float* op = Om[mat] + ((size_t)(b*HH + hh)*CC + c0 + rg*16)*DHH + m;
        #pragma unroll
        for (int r = 0; r < 16; r++) op[r*DHH] = acc[r];
    }
}

// ---- K1b: qp = q@w1q^T, kp = k@w1k^T ----
__global__ void k_qpkp(const float* __restrict__ w1_, int l){
    __shared__ float qs[256][17];
    __shared__ float ks2[256][17];
    __shared__ float w1qs[16][16], w1ks[16][16];
    int base = blockIdx.x*256;            // over B*H*C
    for (int t = threadIdx.x; t < 4096; t += 256){
        qs[t>>4][t&15]  = g_q[(size_t)base*16 + t];
        ks2[t>>4][t&15] = g_k[(size_t)base*16 + t];
    }
    {
        int mm = threadIdx.x >> 4, nn = threadIdx.x & 15;
        w1qs[mm][nn] = w1_[(l*16+mm)*48 + nn];
        w1ks[mm][nn] = w1_[(l*16+mm)*48 + 16 + nn];
    }
    __syncthreads();
    int tid = threadIdx.x;
    float qv[16], kv[16];
    #pragma unroll
    for (int n = 0; n < 16; n++){ qv[n] = qs[tid][n]; kv[n] = ks2[tid][n]; }
    float aq[16], ak[16];
    #pragma unroll
    for (int mm = 0; mm < 16; mm++){
        float a = 0.f, c = 0.f;
        #pragma unroll
        for (int n = 0; n < 16; n++){ a += w1qs[mm][n]*qv[n]; c += w1ks[mm][n]*kv[n]; }
        aq[mm] = a; ak[mm] = c;
    }
    __syncthreads();
    #pragma unroll
    for (int mm = 0; mm < 16; mm++){ qs[tid][mm] = aq[mm]; ks2[tid][mm] = ak[mm]; }
    __syncthreads();
    for (int t = threadIdx.x; t < 4096; t += 256){
        g_qp[(size_t)base*16 + t] = qs[t>>4][t&15];
        g_kp[(size_t)base*16 + t] = ks2[t>>4][t&15];
    }
}

// ---- K2: second-order attention ----
// block = 256 threads = 8 warps = 8 queries (1 warp/query).
// Lane owns 2 key-pairs (4 keys): pair0 at slot lane, pair1 at slot 32+lane.
// qw stored UNduplicated; read float4 broadcast (4 coeffs/phase), packed via mov.
__global__ void __launch_bounds__(256, 2) k_attn(const float* __restrict__ w1_,
        const float* __restrict__ b1_, const float* __restrict__ w2_,
        const float* __restrict__ b2_, int l){
    __shared__ __align__(16) float qw4[8][16][16];  // unduplicated per-query coeffs
    __shared__ __align__(16) u64 qp2[8][16];        // {qp+b1, qp+b1}
    __shared__ __align__(16) u64 w22[16];           // {w2*0.25, w2*0.25}
    __shared__ __align__(16) u64 k2s[16][65];       // [n][jpair] transposed (130f rows)
    __shared__ __align__(16) u64 kp2s[16][65];      // [m][jpair]
    __shared__ __align__(16) u64 v2s[16][65];       // [m][jpair]

    int b = blockIdx.z, h = blockIdx.y, i0 = blockIdx.x*8;
    int tid = threadIdx.x;
    int warp = tid >> 5, lane = tid & 31;
    int bh = b*HH + h;
    const float* qbase  = g_q  + (size_t)(bh*CC + i0)*16;
    const float* qpb_g  = g_qp + (size_t)(bh*CC + i0)*16;

    if (tid < 128){
        int w = tid >> 4, mm = tid & 15;
        float v = qpb_g[w*16+mm] + b1_[l*16+mm];
        qp2[w][mm] = pk2(v, v);
    }
    if (tid >= 128 && tid < 144){
        float v = w2_[l*16 + (tid-128)]*0.25f;
        w22[tid-128] = pk2(v, v);
    }
    for (int t = tid; t < 2048; t += 256){
        int w = t >> 8, mn = t & 255, mm = mn >> 4, nn = mn & 15;
        qw4[w][mm][nn] = qbase[w*16+nn] * w1_[(l*16+mm)*48 + 32 + nn];
    }
    float b2s = b2_[l]*0.25f;

    const u64 C0 = pk2(0.7978845608f, 0.7978845608f);
    const u64 C1 = pk2(0.03567740814f, 0.03567740814f);
    const u64 HF = pk2(0.5f, 0.5f);

    u64 outp[16];
    #pragma unroll
    for (int mm = 0; mm < 16; mm++) outp[mm] = 0ull;
    u64 S = 0ull;

    const float* kb  = g_k  + (size_t)bh*CC*16;
    const float* kpb = g_kp + (size_t)bh*CC*16;
    const float* vb  = g_v  + (size_t)bh*CC*16;
    float* k2f  = (float*)k2s;    // row stride 130 floats
    float* kp2f = (float*)kp2s;
    float* v2f  = (float*)v2s;

    const u64* kprow = &kp2s[0][lane];   // pair1 at +32
    const u64* vrow  = &v2s[0][lane];
    const u64* qpq   = qp2[warp];

    for (int j0 = 0; j0 < CC; j0 += 128){
        __syncthreads();
        // staging: 2048 floats per array, float4 loads, transposed scalar stores
        #pragma unroll
        for (int it = 0; it < 2; it++){
            int t = (tid + it*256)*4;           // 0..2044, step 4
            int n = t & 15, j = t >> 4;
            float4 vk = *(const float4*)&kb [j0*16 + t];
            float4 vp = *(const float4*)&kpb[j0*16 + t];
            float4 vv = *(const float4*)&vb [j0*16 + t];
            k2f [(n+0)*130 + j] = vk.x; k2f [(n+1)*130 + j] = vk.y;
            k2f [(n+2)*130 + j] = vk.z; k2f [(n+3)*130 + j] = vk.w;
            kp2f[(n+0)*130 + j] = vp.x; kp2f[(n+1)*130 + j] = vp.y;
            kp2f[(n+2)*130 + j] = vp.z; kp2f[(n+3)*130 + j] = vp.w;
            v2f [(n+0)*130 + j] = vv.x; v2f [(n+1)*130 + j] = vv.y;
            v2f [(n+2)*130 + j] = vv.z; v2f [(n+3)*130 + j] = vv.w;
        }
        __syncthreads();

        u64 kj[16][2];
        #pragma unroll
        for (int n = 0; n < 16; n++){ kj[n][0] = k2s[n][lane]; kj[n][1] = k2s[n][32+lane]; }

        u64 sc0 = pk2(b2s, b2s), sc1 = sc0;
        #pragma unroll
        for (int mm = 0; mm < 16; mm++){
            u64 qpv = qpq[mm];
            u64 ra0 = add2(qpv, kprow[mm*65]);
            u64 ra1 = add2(qpv, kprow[mm*65+32]);
            u64 rb0 = 0ull, rb1 = 0ull;
            const float4* qwm = (const float4*)qw4[warp][mm];
            #pragma unroll
            for (int i = 0; i < 4; i++){
                float4 w = qwm[i];
                u64 wx = pk2(w.x, w.x);
                u64 wy = pk2(w.y, w.y);
                u64 wz = pk2(w.z, w.z);
                u64 ww = pk2(w.w, w.w);
                ra0 = fma2(wx, kj[4*i+0][0], ra0);  ra1 = fma2(wx, kj[4*i+0][1], ra1);
                rb0 = fma2(wy, kj[4*i+1][0], rb0);  rb1 = fma2(wy, kj[4*i+1][1], rb1);
                ra0 = fma2(wz, kj[4*i+2][0], ra0);  ra1 = fma2(wz, kj[4*i+2][1], ra1);
                rb0 = fma2(ww, kj[4*i+3][0], rb0);  rb1 = fma2(ww, kj[4*i+3][1], rb1);
            }
            u64 r0 = add2(ra0, rb0);
            u64 r1 = add2(ra1, rb1);
            // fast tanh-form gelu on both pairs
            u64 t0 = mul2(r0, r0);
            u64 t1 = mul2(r1, r1);
            u64 a0 = fma2(C1, t0, C0);
            u64 a1 = fma2(C1, t1, C0);
            u64 u0 = mul2(r0, a0);
            u64 u1 = mul2(r1, a1);
            float ua, ub, uc, ud;
            upk2(u0, ua, ub); upk2(u1, uc, ud);
            u64 th0 = pk2(tanh_ap(ua), tanh_ap(ub));
            u64 th1 = pk2(tanh_ap(uc), tanh_ap(ud));
            u64 hx0 = mul2(r0, HF);
            u64 hx1 = mul2(r1, HF);
            u64 g0 = fma2(hx0, th0, hx0);
            u64 g1 = fma2(hx1, th1, hx1);
            u64 wd = w22[mm];
            sc0 = fma2(wd, g0, sc0);
            sc1 = fma2(wd, g1, sc1);
        }
        // fixed-base softmax (scores bounded far below exp overflow)
        float s00, s01, s10, s11;
        upk2(sc0, s00, s01); upk2(sc1, s10, s11);
        u64 p0 = pk2(__expf(s00), __expf(s01));
        u64 p1 = pk2(__expf(s10), __expf(s11));
        S = add2(S, p0);
        S = add2(S, p1);
        #pragma unroll
        for (int mm = 0; mm < 16; mm++){
            outp[mm] = fma2(p0, vrow[mm*65],    outp[mm]);
            outp[mm] = fma2(p1, vrow[mm*65+32], outp[mm]);
        }
    }

    float sl, sh; upk2(S, sl, sh);
    float Ssum = sl + sh;
    #pragma unroll
    for (int o2 = 16; o2 > 0; o2 >>= 1)
        Ssum += __shfl_xor_sync(0xffffffffu, Ssum, o2);
    float res = 0.f;
    #pragma unroll
    for (int mm = 0; mm < 16; mm++){
        float a, bq; upk2(outp[mm], a, bq);
        float t = a + bq;
        #pragma unroll
        for (int o2 = 16; o2 > 0; o2 >>= 1)
            t += __shfl_xor_sync(0xffffffffu, t, o2);
        if (lane == mm) res = t;
    }
    if (lane < 16)
        g_attn[((size_t)(b*CC + i0 + warp))*DD + h*16 + lane] = res / Ssum;
}

// ---- K3: out projection + residual + LN1 ----
__global__ void k_outln(const float* __restrict__ ow, const float* __restrict__ ob,
                        const float* __restrict__ g1, const float* __restrict__ b1g, int l){
    __shared__ float as_[64][65];
    __shared__ float ws[64][65];
    int b = blockIdx.y, c0 = blockIdx.x*64;
    const float* ap = g_attn + (b*CC + c0)*DD;
    for (int t = threadIdx.x; t < 4096; t += 256){
        as_[t>>6][t&63] = ap[t];
        ws[t>>6][t&63]  = ow[l*4096 + t];
    }
    __syncthreads();
    int o = threadIdx.x & 63, rg = threadIdx.x >> 6;
    float acc[16];
    float bias = ob[l*64 + o];
    #pragma unroll
    for (int r = 0; r < 16; r++) acc[r] = bias;
    for (int n = 0; n < 64; n++){
        float w = ws[o][n];
        #pragma unroll
        for (int r = 0; r < 16; r++) acc[r] += as_[rg*16+r][n]*w;
    }
    const float* hp = g_h + (b*CC + c0)*DD;
    float resv[16];
    #pragma unroll
    for (int r = 0; r < 16; r++) resv[r] = acc[r] + hp[(rg*16+r)*64 + o];
    __syncthreads();
    #pragma unroll
    for (int r = 0; r < 16; r++) as_[rg*16+r][o] = resv[r];
    __syncthreads();
    if (threadIdx.x < 64){
        int r = threadIdx.x;
        float mean = 0.f;
        #pragma unroll
        for (int d = 0; d < 64; d++) mean += as_[r][d];
        mean *= (1.0f/64.0f);
        float var = 0.f;
        #pragma unroll
        for (int d = 0; d < 64; d++){ float t = as_[r][d]-mean; var += t*t; }
        var *= (1.0f/64.0f);
        float rstd = rsqrtf(var + 1e-5f);
        float* hout = g_h + ((size_t)(b*CC + c0 + r))*DD;
        for (int d = 0; d < 64; d++)
            hout[d] = (as_[r][d]-mean)*rstd*g1[l*64+d] + b1g[l*64+d];
    }
}

// ---- K4a: FFN layer 1 (64 -> 256) + GELU ----
__global__ void k_ffn1(const float* __restrict__ fw, const float* __restrict__ fb, int l){
    __shared__ float hs[64][65];
    __shared__ float ws[64][65];
    int b = blockIdx.y, c0 = blockIdx.x*64;
    const float* hp = g_h + (b*CC + c0)*DD;
    for (int t = threadIdx.x; t < 4096; t += 256) hs[t>>6][t&63] = hp[t];
    int o = threadIdx.x & 63, rg = threadIdx.x >> 6;
    for (int oc = 0; oc < 4; oc++){
        __syncthreads();
        for (int t = threadIdx.x; t < 4096; t += 256) ws[t>>6][t&63] = fw[l*16384 + oc*4096 + t];
        __syncthreads();
        int j = oc*64 + o;
        float acc[16];
        float bias = fb[l*256 + j];
        #pragma unroll
        for (int r = 0; r < 16; r++) acc[r] = bias;
        for (int n = 0; n < 64; n++){
            float w = ws[o][n];
            #pragma unroll
            for (int r = 0; r < 16; r++) acc[r] += hs[rg*16+r][n]*w;
        }
        float* tp = g_t + ((size_t)(b*CC + c0 + rg*16))*256 + j;
        #pragma unroll
        for (int r = 0; r < 16; r++) tp[r*256] = gelu_f(acc[r]);
    }
}

// ---- K4b: FFN layer 2 (256 -> 64) + residual + LN2 ----
__global__ void k_ffn2(const float* __restrict__ fw, const float* __restrict__ fb,
                       const float* __restrict__ g2, const float* __restrict__ b2g, int l){
    __shared__ float ts[64][65];
    __shared__ float ws[64][65];
    int b = blockIdx.y, c0 = blockIdx.x*64;
    int o = threadIdx.x & 63, rg = threadIdx.x >> 6;
    float acc[16];
    float bias = fb[l*64 + o];
    #pragma unroll
    for (int r = 0; r < 16; r++) acc[r] = bias;
    for (int nc = 0; nc < 4; nc++){
        __syncthreads();
        for (int t = threadIdx.x; t < 4096; t += 256){
            int row = t >> 6, col = t & 63;
            ts[row][col] = g_t[((size_t)(b*CC + c0 + row))*256 + nc*64 + col];
            ws[row][col] = fw[l*16384 + row*256 + nc*64 + col];
        }
        __syncthreads();
        for (int n = 0; n < 64; n++){
            float w = ws[o][n];
            #pragma unroll
            for (int r = 0; r < 16; r++) acc[r] += ts[rg*16+r][n]*w;
        }
    }
    const float* hp = g_h + (b*CC + c0)*DD;
    float resv[16];
    #pragma unroll
    for (int r = 0; r < 16; r++) resv[r] = acc[r] + hp[(rg*16+r)*64 + o];
    __syncthreads();
    #pragma unroll
    for (int r = 0; r < 16; r++) ts[rg*16+r][o] = resv[r];
    __syncthreads();
    if (threadIdx.x < 64){
        int r = threadIdx.x;
        float mean = 0.f;
        #pragma unroll
        for (int d = 0; d < 64; d++) mean += ts[r][d];
        mean *= (1.0f/64.0f);
        float var = 0.f;
        #pragma unroll
        for (int d = 0; d < 64; d++){ float t = ts[r][d]-mean; var += t*t; }
        var *= (1.0f/64.0f);
        float rstd = rsqrtf(var + 1e-5f);
        float* hout = g_h + ((size_t)(b*CC + c0 + r))*DD;
        for (int d = 0; d < 64; d++)
            hout[d] = (ts[r][d]-mean)*rstd*g2[l*64+d] + b2g[l*64+d];
    }
}

// ---- K5: task-query readout ----
__global__ void k_readout(const float* __restrict__ tq, const float* __restrict__ hw,
                          const float* __restrict__ hbias, float* __restrict__ outp){
    __shared__ float s[CC];
    __shared__ float red[256];
    __shared__ float pooled[DD];
    __shared__ float tqs[DD];
    int b = blockIdx.x, tid = threadIdx.x;
    if (tid < 64) tqs[tid] = tq[tid];
    __syncthreads();
    const float* hbase = g_h + (size_t)b*CC*DD;
    for (int c = tid; c < CC; c += 256){
        float acc = 0.f;
        const float* hr = hbase + c*DD;
        for (int d = 0; d < 64; d++) acc += hr[d]*tqs[d];
        s[c] = acc*0.125f;   // 1/sqrt(64)
    }
    __syncthreads();
    float m = -1e30f;
    for (int c = tid; c < CC; c += 256) m = fmaxf(m, s[c]);
    red[tid] = m; __syncthreads();
    for (int st = 128; st > 0; st >>= 1){ if (tid < st) red[tid] = fmaxf(red[tid], red[tid+st]); __syncthreads(); }
    float mx = red[0];
    __syncthreads();
    float ss = 0.f;
    for (int c = tid; c < CC; c += 256){ float e = expf(s[c]-mx); s[c] = e; ss += e; }
    red[tid] = ss; __syncthreads();
    for (int st = 128; st > 0; st >>= 1){ if (tid < st) red[tid] += red[tid+st]; __syncthreads(); }
    float sum = red[0];
    __syncthreads();
    if (tid < 64){
        float acc = 0.f;
        for (int c = 0; c < CC; c++) acc += s[c]*hbase[c*DD + tid];
        pooled[tid] = acc / sum;
    }
    __syncthreads();
    if (tid < OUTN){
        float acc = hbias[tid];
        for (int d = 0; d < 64; d++) acc += pooled[d]*hw[tid*64+d];
        outp[b*OUTN + tid] = acc;
    }
}

extern "C" void kernel_launch(void* const* d_in, const int* in_sizes, int n_in,
                              void* d_out, int out_size){
    const float* x      = (const float*)d_in[0];
    const float* role   = (const float*)d_in[1];
    const float* fw     = (const float*)d_in[2];
    const float* q_w    = (const float*)d_in[3];
    const float* q_b    = (const float*)d_in[4];
    const float* k_w    = (const float*)d_in[5];
    const float* k_b    = (const float*)d_in[6];
    const float* v_w    = (const float*)d_in[7];
    const float* v_b    = (const float*)d_in[8];
    const float* w1     = (const float*)d_in[9];
    const float* b1     = (const float*)d_in[10];
    const float* w2     = (const float*)d_in[11];
    const float* b2     = (const float*)d_in[12];
    const float* out_w  = (const float*)d_in[13];
    const float* out_b  = (const float*)d_in[14];
    const float* ln1_g  = (const float*)d_in[15];
    const float* ln1_b  = (const float*)d_in[16];
    const float* f1_w   = (const float*)d_in[17];
    const float* f1_b   = (const float*)d_in[18];
    const float* f2_w   = (const float*)d_in[19];
    const float* f2_b   = (const float*)d_in[20];
    const float* ln2_g  = (const float*)d_in[21];
    const float* ln2_b  = (const float*)d_in[22];
    const float* task_q = (const float*)d_in[23];
    const float* head_w = (const float*)d_in[24];
    const float* head_b = (const float*)d_in[25];
    float* outp = (float*)d_out;

    k_encode<<<(BB*CC*DD + 255)/256, 256>>>(x, role, fw);
    for (int l = 0; l < LL; l++){
        dim3 g1(CC/64, BB);
        k_qkv<<<g1, 256>>>(q_w, q_b, k_w, k_b, v_w, v_b, l);
        k_qpkp<<<(BB*HH*CC)/256, 256>>>(w1, l);
        dim3 ga(CC/8, HH, BB);
        k_attn<<<ga, 256>>>(w1, b1, w2, b2, l);
        k_outln<<<g1, 256>>>(out_w, out_b, ln1_g, ln1_b, l);
        k_ffn1<<<g1, 256>>>(f1_w, f1_b, l);
        k_ffn2<<<g1, 256>>>(f2_w, f2_b, ln2_g, ln2_b, l);
    }
    k_readout<<<BB, 256>>>(task_q, head_w, head_b, outp);
}